// round 1
// baseline (speedup 1.0000x reference)
#include <cuda_runtime.h>
#include <math.h>

// Problem constants (fixed by setup_inputs): B=2, S=2048, C=64, F=64, K=3
#define Bn   2
#define Sn   2048
#define Cn   64
#define Fn   64
#define Kt   3
#define Mtot (Bn * Sn)     // 4096 rows (b*S + i)
#define Nn   (Fn * Kt)     // 192 cols  (k*F + f)

// Scratch for the factored inner product D[r][k*F+f] = sum_c x[r][c] * kernel[f][c][k]
__device__ float g_D[Mtot * Nn];   // 4096*192*4B = 3.1 MB (static device global, no alloc)

// ---------------------------------------------------------------------------
// Kernel 1: GEMM  D = X (4096x64) * W (64x192), W[n=k*64+f][c] = kernel[f][c][k]
// Block tile: 64 rows x 96 cols, 256 threads, thread tile 8m x 3n.
// smem: xs 16KB + ws 24KB = 40KB (under 48KB static limit).
// ---------------------------------------------------------------------------
__global__ __launch_bounds__(256) void ddc_gemm_kernel(
    const float* __restrict__ x, const float* __restrict__ kw)
{
    __shared__ float xs[64][Cn];     // [m][c]
    __shared__ float ws[Cn][96];     // [c][n_local]

    const int tid = threadIdx.x;
    const int row0 = blockIdx.x * 64;   // grid.x = Mtot/64 = 64
    const int ncol0 = blockIdx.y * 96;  // grid.y = 2

    // Load X tile: 64*64 floats, coalesced.
    #pragma unroll
    for (int idx = tid; idx < 64 * Cn; idx += 256) {
        int m = idx >> 6, c = idx & 63;
        xs[m][c] = x[(row0 + m) * Cn + c];
    }
    // Load transposed weight tile: ws[c][n] = kernel[f][c][k], n_g = ncol0+n, k=n_g>>6, f=n_g&63
    #pragma unroll
    for (int idx = tid; idx < Cn * 96; idx += 256) {
        int c = idx / 96, n = idx % 96;
        int ng = ncol0 + n;
        int k = ng >> 6, f = ng & 63;
        ws[c][n] = kw[f * (Cn * Kt) + c * Kt + k];
    }
    __syncthreads();

    const int tx = tid & 31;        // n direction, strided by 32
    const int ty = tid >> 5;        // 0..7, m direction
    const int m0 = ty * 8;

    float acc[8][3];
    #pragma unroll
    for (int i = 0; i < 8; i++)
        #pragma unroll
        for (int j = 0; j < 3; j++) acc[i][j] = 0.0f;

    #pragma unroll 8
    for (int c = 0; c < Cn; c++) {
        float xv[8], wv[3];
        #pragma unroll
        for (int i = 0; i < 8; i++) xv[i] = xs[m0 + i][c];       // warp-broadcast
        #pragma unroll
        for (int j = 0; j < 3; j++) wv[j] = ws[c][tx + j * 32];  // conflict-free
        #pragma unroll
        for (int i = 0; i < 8; i++)
            #pragma unroll
            for (int j = 0; j < 3; j++)
                acc[i][j] = fmaf(xv[i], wv[j], acc[i][j]);
    }

    #pragma unroll
    for (int i = 0; i < 8; i++) {
        int r = row0 + m0 + i;
        #pragma unroll
        for (int j = 0; j < 3; j++)
            g_D[r * Nn + ncol0 + tx + j * 32] = acc[i][j];
    }
}

// ---------------------------------------------------------------------------
// Kernel 2: gather + lerp epilogue.
// y[b,s,f] = sum_k (1-w_f)*D[b, clip(s-k*dil+I_f)] + w_f*D[b, clip(.+1)]
// Block: 256 threads = 4 s-rows x 64 f. Grid = Mtot/4 = 1024.
// ---------------------------------------------------------------------------
__global__ __launch_bounds__(256) void ddc_gather_kernel(
    const float* __restrict__ ow, const void* __restrict__ dil_ptr,
    float* __restrict__ out)
{
    __shared__ float sw[Fn];
    __shared__ int   sI[Fn];
    __shared__ int   s_dil;

    const int tid = threadIdx.x;
    if (tid < Fn) {
        // Defensive dilation decode: int32/int64 read 2 directly (little-endian);
        // float32 2.0f has a huge int bit pattern -> reinterpret.
        int d = *(const int*)dil_ptr;
        if (d < 1 || d > 65536) d = (int)(*(const float*)dil_ptr);
        if (tid == 0) s_dil = d;

        float max_offset = 0.5f * (float)Sn / (float)(d * Kt);
        float o = ow[tid];
        float off = -max_offset / (1.0f + expf(-o));   // -sigmoid(o)*max_offset
        float fl = floorf(off);
        sI[tid] = (int)fl;
        sw[tid] = off - fl;
    }
    __syncthreads();

    const int f  = tid & 63;
    const int sl = tid >> 6;
    const int rq = blockIdx.x * 4 + sl;   // global b*S + s
    const int b  = rq >> 11;              // S = 2048
    const int s  = rq & (Sn - 1);

    const float w = sw[f];
    const int   I = sI[f];
    const int   d = s_dil;
    const int   rb = b * Sn;

    float y = 0.0f;
    #pragma unroll
    for (int k = 0; k < Kt; k++) {
        int i0  = s - k * d + I;
        int i0c = min(max(i0, 0), Sn - 1);
        int i1c = min(max(i0 + 1, 0), Sn - 1);
        float d0 = g_D[(rb + i0c) * Nn + k * Fn + f];
        float d1 = g_D[(rb + i1c) * Nn + k * Fn + f];
        y += d0 + w * (d1 - d0);
    }
    out[rq * Fn + f] = y;   // fully coalesced: rq*64+f == blockIdx.x*256+tid
}

// ---------------------------------------------------------------------------
extern "C" void kernel_launch(void* const* d_in, const int* in_sizes, int n_in,
                              void* d_out, int out_size)
{
    const float* x   = (const float*)d_in[0];   // (B,S,C) f32
    const float* kw  = (const float*)d_in[1];   // (F,C,K) f32
    const float* ow  = (const float*)d_in[2];   // (F,)    f32
    const void*  dil = d_in[3];                 // scalar dilation_rate

    dim3 ggrid(Mtot / 64, 2);
    ddc_gemm_kernel<<<ggrid, 256>>>(x, kw);
    ddc_gather_kernel<<<Mtot / 4, 256>>>(ow, dil, (float*)d_out);
}